// round 1
// baseline (speedup 1.0000x reference)
#include <cuda_runtime.h>

// ---------------------------------------------------------------------------
// GCN_OUTPRODUCT: B=16, C=32, T=128, J=25, O=64
// Pipeline: graph precompute -> branches (graph conv, 1x1 convs, quadratic
// form) -> temporal conv (3,1) -> batchnorm (training stats) -> affine out.
// ---------------------------------------------------------------------------

#define NB 16
#define NC 32
#define NT 128
#define NJ 25
#define NO 64
#define EPSBN 1e-5f

// scratch (static device allocations; allowed)
__device__ __align__(16) float g_An[NJ * NJ];
__device__ __align__(16) float g_A2[NJ * NJ];
__device__ __align__(16) float g_W3t[1024 * 32];        // [cc][o]
__device__ __align__(16) float g_Wtt[96 * 3 * 64];      // [(i*3+dt)][o]
__device__ __align__(16) float g_xc[NB * 96 * NT * NJ]; // concat branches
__device__ __align__(16) float g_y[NB * NO * NT * NJ];  // post-relu conv out
__device__ __align__(16) float g_part[1024 * 128];      // per-block BN partials
__device__ __align__(16) float g_scsh[128];             // scale / shift

// ---------------------------------------------------------------------------
// K0: graph matrices + weight transposes
// ---------------------------------------------------------------------------
__global__ void k0_prep(const float* __restrict__ A,
                        const float* __restrict__ W3,
                        const float* __restrict__ Wt) {
    int tid = threadIdx.x;
    if (blockIdx.x == 0) {
        __shared__ float d[NJ], dw[NJ];
        if (tid < NJ) {
            float s = 0.f;
            for (int k = 0; k < NJ; ++k) s += A[tid * NJ + k];
            d[tid] = s;
            dw[tid] = s - A[tid * NJ + tid];  // Aw = A - I row sum
        }
        __syncthreads();
        for (int idx = tid; idx < NJ * NJ; idx += blockDim.x) {
            int j = idx / NJ, k = idx % NJ;
            g_An[idx] = A[idx] * rsqrtf(d[j] * d[k]);
            g_A2[idx] = (j == k) ? dw[j] : -A[idx];
        }
    }
    int gtid = blockIdx.x * blockDim.x + tid;
    int stride = gridDim.x * blockDim.x;
    for (int idx = gtid; idx < 32 * 1024; idx += stride) {
        int o = idx >> 10, cc = idx & 1023;
        g_W3t[cc * 32 + o] = W3[idx];
    }
    for (int idx = gtid; idx < 64 * 288; idx += stride) {
        int o = idx / 288, r = idx % 288;
        g_Wtt[r * 64 + o] = Wt[idx];
    }
}

// ---------------------------------------------------------------------------
// K1: per (b, 4-t chunk): graph convs + pw convs + quadratic-form branch
// grid = 16 * 32 = 512 blocks, 256 threads
// ---------------------------------------------------------------------------
__global__ void __launch_bounds__(256) k1_branches(
    const float* __restrict__ x,
    const float* __restrict__ W1, const float* __restrict__ b1,
    const float* __restrict__ W2, const float* __restrict__ b2,
    const float* __restrict__ b3) {
    __shared__ float sA[32 * 100];   // x slice, later G1
    __shared__ float sB[32 * 100];   // G2
    __shared__ float sAn[NJ * NJ];
    __shared__ float sA2[NJ * NJ];
    __shared__ float sW1[32 * 32];
    __shared__ float sW2[32 * 32];

    int tid = threadIdx.x;
    int b = blockIdx.x >> 5;
    int t0 = (blockIdx.x & 31) * 4;

    // load x slice [c][tt*25+j]
    for (int idx = tid; idx < 3200; idx += 256) {
        int c = idx / 100, q = idx % 100;
        int tt = q / 25, j = q % 25;
        sA[idx] = x[((b * 32 + c) * 128 + t0 + tt) * 25 + j];
    }
    for (int idx = tid; idx < NJ * NJ; idx += 256) {
        sAn[idx] = g_An[idx];
        sA2[idx] = g_A2[idx];
    }
    for (int idx = tid; idx < 1024; idx += 256) {
        sW1[idx] = W1[idx];
        sW2[idx] = W2[idx];
    }
    __syncthreads();

    // graph convs -> registers (so G1 can overwrite x buffer)
    float r1[13], r2[13];
#pragma unroll
    for (int it = 0; it < 13; ++it) {
        int idx = tid + it * 256;
        float a1 = 0.f, a2 = 0.f;
        if (idx < 3200) {
            int c = idx / 100, q = idx % 100;
            int tt = q / 25, k = q % 25;
            const float* xr = &sA[c * 100 + tt * 25];
#pragma unroll
            for (int j = 0; j < 25; ++j) {
                float xv = xr[j];
                a1 += xv * sAn[j * 25 + k];
                a2 += xv * sA2[j * 25 + k];
            }
        }
        r1[it] = a1;
        r2[it] = a2;
    }
    __syncthreads();
#pragma unroll
    for (int it = 0; it < 13; ++it) {
        int idx = tid + it * 256;
        if (idx < 3200) { sA[idx] = r1[it]; sB[idx] = r2[it]; }
    }
    __syncthreads();

    // pointwise convs: x1o (channels 0..31), x2o (channels 32..63)
    for (int idx = tid; idx < 6400; idx += 256) {
        int which = idx >= 3200 ? 1 : 0;
        int r = idx - which * 3200;
        int o = r / 100, p = r % 100;
        const float* G = which ? sB : sA;
        const float* W = which ? &sW2[o * 32] : &sW1[o * 32];
        float acc = which ? __ldg(&b2[o]) : __ldg(&b1[o]);
#pragma unroll
        for (int c = 0; c < 32; ++c) acc += W[c] * G[c * 100 + p];
        acc = fmaxf(acc, 0.f);
        int tt = p / 25, k = p % 25;
        g_xc[((b * 96 + which * 32 + o) * 128 + t0 + tt) * 25 + k] = acc;
    }

    // quadratic form branch: x3o[o,p] = relu(b3[o] + sum_{c1,c2} W3[o,c1,c2] v[c1] v[c2])
    int og = tid >> 5;       // 0..7 -> 4 output channels each
    int pg = tid & 31;       // 0..31 -> up to 4 positions each
    int ob = og * 4;
    int p0 = pg, p1 = pg + 32, p2 = pg + 64;
    bool v3 = (pg < 4);
    int p3 = v3 ? pg + 96 : 99;  // clamp (masked on store)

    float a0[4] = {0, 0, 0, 0}, a1v[4] = {0, 0, 0, 0};
    float a2v[4] = {0, 0, 0, 0}, a3v[4] = {0, 0, 0, 0};
    const float4* W3t4 = reinterpret_cast<const float4*>(g_W3t);
    int obq = ob >> 2;

    for (int c1 = 0; c1 < 32; ++c1) {
        float v10 = sB[c1 * 100 + p0];
        float v11 = sB[c1 * 100 + p1];
        float v12 = sB[c1 * 100 + p2];
        float v13 = sB[c1 * 100 + p3];
        int base = (c1 * 32) * 8 + obq;  // float4 index of W3t[(c1*32+c2)*32 + ob]
#pragma unroll 4
        for (int c2 = 0; c2 < 32; ++c2) {
            float4 w = __ldg(&W3t4[base + c2 * 8]);
            float q0 = v10 * sB[c2 * 100 + p0];
            float q1 = v11 * sB[c2 * 100 + p1];
            float q2 = v12 * sB[c2 * 100 + p2];
            float q3 = v13 * sB[c2 * 100 + p3];
            a0[0] += w.x * q0; a0[1] += w.y * q0; a0[2] += w.z * q0; a0[3] += w.w * q0;
            a1v[0] += w.x * q1; a1v[1] += w.y * q1; a1v[2] += w.z * q1; a1v[3] += w.w * q1;
            a2v[0] += w.x * q2; a2v[1] += w.y * q2; a2v[2] += w.z * q2; a2v[3] += w.w * q2;
            a3v[0] += w.x * q3; a3v[1] += w.y * q3; a3v[2] += w.z * q3; a3v[3] += w.w * q3;
        }
    }
    float bb[4];
#pragma unroll
    for (int o = 0; o < 4; ++o) bb[o] = __ldg(&b3[ob + o]);

#pragma unroll
    for (int pi = 0; pi < 4; ++pi) {
        const float* ac = (pi == 0) ? a0 : (pi == 1) ? a1v : (pi == 2) ? a2v : a3v;
        int p = (pi == 0) ? p0 : (pi == 1) ? p1 : (pi == 2) ? p2 : p3;
        if (pi == 3 && !v3) continue;
        int tt = p / 25, k = p % 25;
#pragma unroll
        for (int o = 0; o < 4; ++o) {
            float v = fmaxf(ac[o] + bb[o], 0.f);
            g_xc[((b * 96 + 64 + ob + o) * 128 + t0 + tt) * 25 + k] = v;
        }
    }
}

// ---------------------------------------------------------------------------
// K2: temporal conv (3,1) + bias + relu + per-block BN partial sums
// grid = 16 * 64 = 1024 blocks (2 t's each), 256 threads
// ---------------------------------------------------------------------------
__global__ void __launch_bounds__(256) k2_tconv(const float* __restrict__ bt) {
    __shared__ float sxc[96 * 100];  // [i][tl*25+j], tl in [0,4): t0-1..t0+2
    int tid = threadIdx.x;
    int b = blockIdx.x >> 6;
    int t0 = (blockIdx.x & 63) * 2;

    for (int idx = tid; idx < 9600; idx += 256) {
        int i = idx / 100, q = idx % 100;
        int tl = q / 25, j = q % 25;
        int t = t0 - 1 + tl;
        sxc[idx] = (t >= 0 && t < 128) ? g_xc[((b * 96 + i) * 128 + t) * 25 + j] : 0.f;
    }
    __syncthreads();

    int og = tid >> 4, pg = tid & 15;  // 16 o-groups x 16 p-groups
    int ob = og * 4;
    int p0 = pg, p1 = pg + 16, p2 = pg + 32;
    bool v3 = (pg < 2);
    int p3 = v3 ? pg + 48 : 49;

    float a0[4] = {0, 0, 0, 0}, a1[4] = {0, 0, 0, 0};
    float a2[4] = {0, 0, 0, 0}, a3[4] = {0, 0, 0, 0};
    const float4* Wtt4 = reinterpret_cast<const float4*>(g_Wtt);
    int obq = ob >> 2;

    for (int i = 0; i < 96; ++i) {
        const float* row = &sxc[i * 100];
#pragma unroll
        for (int dt = 0; dt < 3; ++dt) {
            float4 w = __ldg(&Wtt4[(i * 3 + dt) * 16 + obq]);
            int off = dt * 25;
            float x0 = row[p0 + off];
            float x1 = row[p1 + off];
            float x2 = row[p2 + off];
            float x3 = row[p3 + off];
            a0[0] += w.x * x0; a0[1] += w.y * x0; a0[2] += w.z * x0; a0[3] += w.w * x0;
            a1[0] += w.x * x1; a1[1] += w.y * x1; a1[2] += w.z * x1; a1[3] += w.w * x1;
            a2[0] += w.x * x2; a2[1] += w.y * x2; a2[2] += w.z * x2; a2[3] += w.w * x2;
            a3[0] += w.x * x3; a3[1] += w.y * x3; a3[2] += w.z * x3; a3[3] += w.w * x3;
        }
    }

    float bv[4], ls[4] = {0, 0, 0, 0}, ls2[4] = {0, 0, 0, 0};
#pragma unroll
    for (int o = 0; o < 4; ++o) bv[o] = __ldg(&bt[ob + o]);

#pragma unroll
    for (int pi = 0; pi < 4; ++pi) {
        const float* ac = (pi == 0) ? a0 : (pi == 1) ? a1 : (pi == 2) ? a2 : a3;
        int p = (pi == 0) ? p0 : (pi == 1) ? p1 : (pi == 2) ? p2 : p3;
        if (pi == 3 && !v3) continue;
        int tt = p / 25, k = p % 25;
#pragma unroll
        for (int o = 0; o < 4; ++o) {
            float y = fmaxf(ac[o] + bv[o], 0.f);
            g_y[((b * 64 + ob + o) * 128 + t0 + tt) * 25 + k] = y;
            ls[o] += y;
            ls2[o] += y * y;
        }
    }

    // deterministic per-block reduction into g_part (reuse sxc)
    __syncthreads();
    float* red = sxc;          // [16][64] sums
    float* red2 = sxc + 1024;  // [16][64] sumsqs
#pragma unroll
    for (int o = 0; o < 4; ++o) {
        red[pg * 64 + ob + o] = ls[o];
        red2[pg * 64 + ob + o] = ls2[o];
    }
    __syncthreads();
    if (tid < 64) {
        float s = 0.f, s2 = 0.f;
#pragma unroll
        for (int g = 0; g < 16; ++g) {
            s += red[g * 64 + tid];
            s2 += red2[g * 64 + tid];
        }
        g_part[blockIdx.x * 128 + tid] = s;
        g_part[blockIdx.x * 128 + 64 + tid] = s2;
    }
}

// ---------------------------------------------------------------------------
// K3: BN stats -> scale/shift (deterministic)
// ---------------------------------------------------------------------------
__global__ void k3_stats(const float* __restrict__ gamma,
                         const float* __restrict__ beta) {
    __shared__ float rs[4 * 64], rs2[4 * 64];
    int tid = threadIdx.x;          // 256
    int o = tid & 63, part = tid >> 6;
    float s = 0.f, s2 = 0.f;
    for (int blk = part; blk < 1024; blk += 4) {
        s += g_part[blk * 128 + o];
        s2 += g_part[blk * 128 + 64 + o];
    }
    rs[part * 64 + o] = s;
    rs2[part * 64 + o] = s2;
    __syncthreads();
    if (tid < 64) {
        float S = rs[tid] + rs[64 + tid] + rs[128 + tid] + rs[192 + tid];
        float S2 = rs2[tid] + rs2[64 + tid] + rs2[128 + tid] + rs2[192 + tid];
        const float N = (float)(NB * NT * NJ);
        float mean = S / N;
        float var = S2 / N - mean * mean;
        float sc = __ldg(&gamma[tid]) * rsqrtf(var + EPSBN);
        g_scsh[tid] = sc;
        g_scsh[64 + tid] = __ldg(&beta[tid]) - mean * sc;
    }
}

// ---------------------------------------------------------------------------
// K4: affine normalize to output (float4)
// ---------------------------------------------------------------------------
__global__ void k4_norm(float* __restrict__ out) {
    int idx = blockIdx.x * blockDim.x + threadIdx.x;  // float4 index
    const int total4 = NB * NO * NT * NJ / 4;         // 819200
    if (idx >= total4) return;
    int ch = (idx / 800) & 63;  // 3200 floats = 800 float4 per (b,o)
    float sc = g_scsh[ch], sh = g_scsh[64 + ch];
    const float4* y4 = reinterpret_cast<const float4*>(g_y);
    float4 v = y4[idx];
    v.x = sc * v.x + sh;
    v.y = sc * v.y + sh;
    v.z = sc * v.z + sh;
    v.w = sc * v.w + sh;
    reinterpret_cast<float4*>(out)[idx] = v;
}

// ---------------------------------------------------------------------------
extern "C" void kernel_launch(void* const* d_in, const int* in_sizes, int n_in,
                              void* d_out, int out_size) {
    const float* x = (const float*)d_in[0];
    const float* A = (const float*)d_in[1];
    const float* W1 = (const float*)d_in[2];
    const float* b1 = (const float*)d_in[3];
    const float* W2 = (const float*)d_in[4];
    const float* b2 = (const float*)d_in[5];
    const float* W3 = (const float*)d_in[6];
    const float* b3 = (const float*)d_in[7];
    const float* Wt = (const float*)d_in[8];
    const float* bt = (const float*)d_in[9];
    const float* gamma = (const float*)d_in[10];
    const float* beta = (const float*)d_in[11];

    k0_prep<<<64, 256>>>(A, W3, Wt);
    k1_branches<<<512, 256>>>(x, W1, b1, W2, b2, b3);
    k2_tconv<<<1024, 256>>>(bt);
    k3_stats<<<1, 256>>>(gamma, beta);
    k4_norm<<<3200, 256>>>((float*)d_out);
}

// round 2
// speedup vs baseline: 1.3417x; 1.3417x over previous
#include <cuda_runtime.h>

// ---------------------------------------------------------------------------
// GCN_OUTPRODUCT: B=16, C=32, T=128, J=25, O=64
// ---------------------------------------------------------------------------

#define NB 16
#define NC 32
#define NT 128
#define NJ 25
#define NO 64
#define EPSBN 1e-5f

// scratch (static device allocations; allowed)
__device__ __align__(16) float g_An[NJ * NJ];
__device__ __align__(16) float g_A2[NJ * NJ];
__device__ __align__(16) float g_Wsym[544 * 32];        // [(c1*17+d)][o]
__device__ __align__(16) float g_Wtt[96 * 3 * 64];      // [(i*3+dt)][o]
__device__ __align__(16) float g_xc[NB * 96 * NT * NJ]; // concat branches
__device__ __align__(16) float g_y[NB * NO * NT * NJ];  // post-relu conv out
__device__ __align__(16) float g_part[128 * 1024];      // [chan-stat][block]
__device__ __align__(16) float g_scsh[128];             // scale / shift

// ---------------------------------------------------------------------------
// K0: graph matrices + symmetrized W3 + transposed Wt
// ---------------------------------------------------------------------------
__global__ void k0_prep(const float* __restrict__ A,
                        const float* __restrict__ W3,
                        const float* __restrict__ Wt) {
    int tid = threadIdx.x;
    if (blockIdx.x == 0) {
        __shared__ float d[NJ], dw[NJ];
        if (tid < NJ) {
            float s = 0.f;
            for (int k = 0; k < NJ; ++k) s += A[tid * NJ + k];
            d[tid] = s;
            dw[tid] = s - A[tid * NJ + tid];  // Aw = A - I row sum
        }
        __syncthreads();
        for (int idx = tid; idx < NJ * NJ; idx += blockDim.x) {
            int j = idx / NJ, k = idx % NJ;
            g_An[idx] = A[idx] * rsqrtf(d[j] * d[k]);
            g_A2[idx] = (j == k) ? dw[j] : -A[idx];
        }
    }
    int gtid = blockIdx.x * blockDim.x + tid;
    int stride = gridDim.x * blockDim.x;
    // Wsym[(c1*17+d)*32 + o]: symmetric pair coefficients of W3[o, c1*32+c2]
    for (int idx = gtid; idx < 544 * 32; idx += stride) {
        int r = idx >> 5, o = idx & 31;
        int c1 = r / 17, dd = r % 17;
        int c2 = (c1 + dd) & 31;
        float v;
        if (dd == 0) {
            v = W3[o * 1024 + c1 * 32 + c1];
        } else {
            v = W3[o * 1024 + c1 * 32 + c2] + W3[o * 1024 + c2 * 32 + c1];
            if (dd == 16) v *= 0.5f;  // pairs with distance 16 enumerated twice
        }
        g_Wsym[r * 32 + o] = v;
    }
    for (int idx = gtid; idx < 64 * 288; idx += stride) {
        int o = idx / 288, r = idx % 288;
        g_Wtt[r * 64 + o] = Wt[idx];
    }
}

// ---------------------------------------------------------------------------
// K1: per (b, 4-t chunk): graph convs + pw convs + quadratic-form branch
// grid = 16 * 32 = 512 blocks, 256 threads
// ---------------------------------------------------------------------------
__global__ void __launch_bounds__(256) k1_branches(
    const float* __restrict__ x,
    const float* __restrict__ W1, const float* __restrict__ b1,
    const float* __restrict__ W2, const float* __restrict__ b2,
    const float* __restrict__ b3) {
    __shared__ float sA[32 * 100];   // x slice, later G1
    __shared__ float sB[32 * 100];   // G2
    __shared__ float sAn[NJ * NJ];
    __shared__ float sA2[NJ * NJ];
    __shared__ float sW1[32 * 32];
    __shared__ float sW2[32 * 32];

    int tid = threadIdx.x;
    int b = blockIdx.x >> 5;
    int t0 = (blockIdx.x & 31) * 4;

    // load x slice [c][tt*25+j]
    for (int idx = tid; idx < 3200; idx += 256) {
        int c = idx / 100, q = idx % 100;
        int tt = q / 25, j = q % 25;
        sA[idx] = x[((b * 32 + c) * 128 + t0 + tt) * 25 + j];
    }
    for (int idx = tid; idx < NJ * NJ; idx += 256) {
        sAn[idx] = g_An[idx];
        sA2[idx] = g_A2[idx];
    }
    for (int idx = tid; idx < 1024; idx += 256) {
        sW1[idx] = W1[idx];
        sW2[idx] = W2[idx];
    }
    __syncthreads();

    // graph convs -> registers (so G1 can overwrite x buffer)
    float r1[13], r2[13];
#pragma unroll
    for (int it = 0; it < 13; ++it) {
        int idx = tid + it * 256;
        float a1 = 0.f, a2 = 0.f;
        if (idx < 3200) {
            int c = idx / 100, q = idx % 100;
            int tt = q / 25, k = q % 25;
            const float* xr = &sA[c * 100 + tt * 25];
#pragma unroll
            for (int j = 0; j < 25; ++j) {
                float xv = xr[j];
                a1 += xv * sAn[j * 25 + k];
                a2 += xv * sA2[j * 25 + k];
            }
        }
        r1[it] = a1;
        r2[it] = a2;
    }
    __syncthreads();
#pragma unroll
    for (int it = 0; it < 13; ++it) {
        int idx = tid + it * 256;
        if (idx < 3200) { sA[idx] = r1[it]; sB[idx] = r2[it]; }
    }
    __syncthreads();

    // pointwise convs: x1o (channels 0..31), x2o (channels 32..63)
    for (int idx = tid; idx < 6400; idx += 256) {
        int which = idx >= 3200 ? 1 : 0;
        int r = idx - which * 3200;
        int o = r / 100, p = r % 100;
        const float* G = which ? sB : sA;
        const float* W = which ? &sW2[o * 32] : &sW1[o * 32];
        float acc = which ? __ldg(&b2[o]) : __ldg(&b1[o]);
#pragma unroll
        for (int c = 0; c < 32; ++c) acc += W[c] * G[c * 100 + p];
        acc = fmaxf(acc, 0.f);
        int tt = p / 25, k = p % 25;
        g_xc[((b * 96 + which * 32 + o) * 128 + t0 + tt) * 25 + k] = acc;
    }

    // quadratic form: x3o[o,p] = relu(b3[o] + v^T Msym_o v), symmetric pairs
    // enumerated as (c1, c2=(c1+d)&31), d=0..16. o-tile=8, pos-tile=2.
    int og = tid >> 6;       // 0..3 -> 8 output channels each
    int pg = tid & 63;       // 0..63 -> up to 2 positions each
    int ob = og * 8;
    int p0 = pg;
    bool has1 = (pg < 36);
    int p1 = has1 ? pg + 64 : pg;

    float acc0[8] = {0, 0, 0, 0, 0, 0, 0, 0};
    float acc1[8] = {0, 0, 0, 0, 0, 0, 0, 0};
    const float4* Ws4 = reinterpret_cast<const float4*>(g_Wsym);
    int oq = og * 2;

#pragma unroll 1
    for (int c1 = 0; c1 < 32; ++c1) {
        float u0 = sB[c1 * 100 + p0];
        float u1 = sB[c1 * 100 + p1];
        int rbase = (c1 * 17) * 8 + oq;
#pragma unroll
        for (int dd = 0; dd < 17; ++dd) {
            int c2 = (c1 + dd) & 31;
            const float* row = &sB[c2 * 100];
            float q0 = u0 * row[p0];
            float q1 = u1 * row[p1];
            float4 wa = __ldg(&Ws4[rbase + dd * 8]);
            float4 wb = __ldg(&Ws4[rbase + dd * 8 + 1]);
            acc0[0] += wa.x * q0; acc0[1] += wa.y * q0;
            acc0[2] += wa.z * q0; acc0[3] += wa.w * q0;
            acc0[4] += wb.x * q0; acc0[5] += wb.y * q0;
            acc0[6] += wb.z * q0; acc0[7] += wb.w * q0;
            acc1[0] += wa.x * q1; acc1[1] += wa.y * q1;
            acc1[2] += wa.z * q1; acc1[3] += wa.w * q1;
            acc1[4] += wb.x * q1; acc1[5] += wb.y * q1;
            acc1[6] += wb.z * q1; acc1[7] += wb.w * q1;
        }
    }

    float bb[8];
#pragma unroll
    for (int o = 0; o < 8; ++o) bb[o] = __ldg(&b3[ob + o]);

    {
        int tt = p0 / 25, k = p0 % 25;
#pragma unroll
        for (int o = 0; o < 8; ++o) {
            float v = fmaxf(acc0[o] + bb[o], 0.f);
            g_xc[((b * 96 + 64 + ob + o) * 128 + t0 + tt) * 25 + k] = v;
        }
    }
    if (has1) {
        int tt = p1 / 25, k = p1 % 25;
#pragma unroll
        for (int o = 0; o < 8; ++o) {
            float v = fmaxf(acc1[o] + bb[o], 0.f);
            g_xc[((b * 96 + 64 + ob + o) * 128 + t0 + tt) * 25 + k] = v;
        }
    }
}

// ---------------------------------------------------------------------------
// K2: temporal conv (3,1) + bias + relu + per-block BN partial sums
// grid = 16 * 64 = 1024 blocks (2 t's each), 256 threads
// ---------------------------------------------------------------------------
__global__ void __launch_bounds__(256) k2_tconv(const float* __restrict__ bt) {
    __shared__ float sxc[96 * 100];  // [i][tl*25+j], tl in [0,4): t0-1..t0+2
    int tid = threadIdx.x;
    int b = blockIdx.x >> 6;
    int t0 = (blockIdx.x & 63) * 2;

    for (int idx = tid; idx < 9600; idx += 256) {
        int i = idx / 100, q = idx % 100;
        int tl = q / 25, j = q % 25;
        int t = t0 - 1 + tl;
        sxc[idx] = (t >= 0 && t < 128) ? g_xc[((b * 96 + i) * 128 + t) * 25 + j] : 0.f;
    }
    __syncthreads();

    int og = tid >> 4, pg = tid & 15;  // 16 o-groups x 16 p-groups
    int ob = og * 4;
    int p0 = pg, p1 = pg + 16, p2 = pg + 32;
    bool v3 = (pg < 2);
    int p3 = v3 ? pg + 48 : 49;

    float a0[4] = {0, 0, 0, 0}, a1[4] = {0, 0, 0, 0};
    float a2[4] = {0, 0, 0, 0}, a3[4] = {0, 0, 0, 0};
    const float4* Wtt4 = reinterpret_cast<const float4*>(g_Wtt);
    int obq = ob >> 2;

    for (int i = 0; i < 96; ++i) {
        const float* row = &sxc[i * 100];
#pragma unroll
        for (int dt = 0; dt < 3; ++dt) {
            float4 w = __ldg(&Wtt4[(i * 3 + dt) * 16 + obq]);
            int off = dt * 25;
            float x0 = row[p0 + off];
            float x1 = row[p1 + off];
            float x2 = row[p2 + off];
            float x3 = row[p3 + off];
            a0[0] += w.x * x0; a0[1] += w.y * x0; a0[2] += w.z * x0; a0[3] += w.w * x0;
            a1[0] += w.x * x1; a1[1] += w.y * x1; a1[2] += w.z * x1; a1[3] += w.w * x1;
            a2[0] += w.x * x2; a2[1] += w.y * x2; a2[2] += w.z * x2; a2[3] += w.w * x2;
            a3[0] += w.x * x3; a3[1] += w.y * x3; a3[2] += w.z * x3; a3[3] += w.w * x3;
        }
    }

    float bv[4], ls[4] = {0, 0, 0, 0}, ls2[4] = {0, 0, 0, 0};
#pragma unroll
    for (int o = 0; o < 4; ++o) bv[o] = __ldg(&bt[ob + o]);

#pragma unroll
    for (int pi = 0; pi < 4; ++pi) {
        const float* ac = (pi == 0) ? a0 : (pi == 1) ? a1 : (pi == 2) ? a2 : a3;
        int p = (pi == 0) ? p0 : (pi == 1) ? p1 : (pi == 2) ? p2 : p3;
        if (pi == 3 && !v3) continue;
        int tt = p / 25, k = p % 25;
#pragma unroll
        for (int o = 0; o < 4; ++o) {
            float y = fmaxf(ac[o] + bv[o], 0.f);
            g_y[((b * 64 + ob + o) * 128 + t0 + tt) * 25 + k] = y;
            ls[o] += y;
            ls2[o] += y * y;
        }
    }

    // deterministic per-block reduction, partials transposed: [chan][block]
    __syncthreads();
    float* red = sxc;          // [16][64] sums
    float* red2 = sxc + 1024;  // [16][64] sumsqs
#pragma unroll
    for (int o = 0; o < 4; ++o) {
        red[pg * 64 + ob + o] = ls[o];
        red2[pg * 64 + ob + o] = ls2[o];
    }
    __syncthreads();
    if (tid < 64) {
        float s = 0.f, s2 = 0.f;
#pragma unroll
        for (int g = 0; g < 16; ++g) {
            s += red[g * 64 + tid];
            s2 += red2[g * 64 + tid];
        }
        g_part[tid * 1024 + blockIdx.x] = s;
        g_part[(64 + tid) * 1024 + blockIdx.x] = s2;
    }
}

// ---------------------------------------------------------------------------
// K3: BN stats -> scale/shift (deterministic). grid = 64 (one per channel)
// ---------------------------------------------------------------------------
__global__ void __launch_bounds__(256) k3_stats(const float* __restrict__ gamma,
                                                const float* __restrict__ beta) {
    __shared__ float rs[256], rq[256];
    int tid = threadIdx.x;
    int o = blockIdx.x;
    const float4* ps = reinterpret_cast<const float4*>(&g_part[o * 1024]);
    const float4* pq = reinterpret_cast<const float4*>(&g_part[(64 + o) * 1024]);
    float4 a = ps[tid];
    float4 b = pq[tid];
    rs[tid] = (a.x + a.y) + (a.z + a.w);
    rq[tid] = (b.x + b.y) + (b.z + b.w);
    __syncthreads();
#pragma unroll
    for (int st = 128; st > 0; st >>= 1) {
        if (tid < st) { rs[tid] += rs[tid + st]; rq[tid] += rq[tid + st]; }
        __syncthreads();
    }
    if (tid == 0) {
        const float N = (float)(NB * NT * NJ);
        float mean = rs[0] / N;
        float var = rq[0] / N - mean * mean;
        float sc = __ldg(&gamma[o]) * rsqrtf(var + EPSBN);
        g_scsh[o] = sc;
        g_scsh[64 + o] = __ldg(&beta[o]) - mean * sc;
    }
}

// ---------------------------------------------------------------------------
// K4: affine normalize to output (float4)
// ---------------------------------------------------------------------------
__global__ void k4_norm(float* __restrict__ out) {
    int idx = blockIdx.x * blockDim.x + threadIdx.x;  // float4 index
    const int total4 = NB * NO * NT * NJ / 4;         // 819200
    if (idx >= total4) return;
    int ch = (idx / 800) & 63;  // 3200 floats = 800 float4 per (b,o)
    float sc = g_scsh[ch], sh = g_scsh[64 + ch];
    const float4* y4 = reinterpret_cast<const float4*>(g_y);
    float4 v = y4[idx];
    v.x = sc * v.x + sh;
    v.y = sc * v.y + sh;
    v.z = sc * v.z + sh;
    v.w = sc * v.w + sh;
    reinterpret_cast<float4*>(out)[idx] = v;
}

// ---------------------------------------------------------------------------
extern "C" void kernel_launch(void* const* d_in, const int* in_sizes, int n_in,
                              void* d_out, int out_size) {
    const float* x = (const float*)d_in[0];
    const float* A = (const float*)d_in[1];
    const float* W1 = (const float*)d_in[2];
    const float* b1 = (const float*)d_in[3];
    const float* W2 = (const float*)d_in[4];
    const float* b2 = (const float*)d_in[5];
    const float* W3 = (const float*)d_in[6];
    const float* b3 = (const float*)d_in[7];
    const float* Wt = (const float*)d_in[8];
    const float* bt = (const float*)d_in[9];
    const float* gamma = (const float*)d_in[10];
    const float* beta = (const float*)d_in[11];

    k0_prep<<<64, 256>>>(A, W3, Wt);
    k1_branches<<<512, 256>>>(x, W1, b1, W2, b2, b3);
    k2_tconv<<<1024, 256>>>(bt);
    k3_stats<<<64, 256>>>(gamma, beta);
    k4_norm<<<3200, 256>>>((float*)d_out);
}

// round 3
// speedup vs baseline: 1.5085x; 1.1243x over previous
#include <cuda_runtime.h>
#include <cstdint>

// ---------------------------------------------------------------------------
// GCN_OUTPRODUCT: B=16, C=32, T=128, J=25, O=64
// ---------------------------------------------------------------------------

#define NB 16
#define NC 32
#define NT 128
#define NJ 25
#define NO 64
#define EPSBN 1e-5f

// scratch (static device allocations; allowed)
__device__ __align__(16) float g_An[NJ * NJ];
__device__ __align__(16) float g_A2[NJ * NJ];
__device__ __align__(16) float g_Wsym[544 * 32];        // [(c1*17+d)][o]
__device__ __align__(16) float g_WAh[64 * 288];         // Wt tf32 hi, [o][k]
__device__ __align__(16) float g_WAl[64 * 288];         // Wt tf32 lo, [o][k]
__device__ __align__(16) float g_xc[NB * 96 * NT * NJ]; // concat branches
__device__ __align__(16) float g_y[NB * NO * NT * NJ];  // post-relu conv out
__device__ __align__(16) float g_part[128 * 256];       // [chan-stat][block]
__device__ __align__(16) float g_scsh[128];             // scale / shift

// ---------------------------------------------------------------------------
// mma.sync tf32 helpers
// ---------------------------------------------------------------------------
__device__ __forceinline__ uint32_t f2tf32(float x) {
    uint32_t r;
    asm("cvt.rna.tf32.f32 %0, %1;" : "=r"(r) : "f"(x));
    return r;
}

__device__ __forceinline__ void mma_tf32(float* d,
                                         uint32_t a0, uint32_t a1,
                                         uint32_t a2, uint32_t a3,
                                         uint32_t b0, uint32_t b1) {
    asm volatile(
        "mma.sync.aligned.m16n8k8.row.col.f32.tf32.tf32.f32 "
        "{%0,%1,%2,%3}, {%4,%5,%6,%7}, {%8,%9}, {%0,%1,%2,%3};"
        : "+f"(d[0]), "+f"(d[1]), "+f"(d[2]), "+f"(d[3])
        : "r"(a0), "r"(a1), "r"(a2), "r"(a3), "r"(b0), "r"(b1));
}

// ---------------------------------------------------------------------------
// K0: graph matrices + symmetrized W3 + tf32 hi/lo split of Wt
// ---------------------------------------------------------------------------
__global__ void k0_prep(const float* __restrict__ A,
                        const float* __restrict__ W3,
                        const float* __restrict__ Wt) {
    int tid = threadIdx.x;
    if (blockIdx.x == 0) {
        __shared__ float d[NJ], dw[NJ];
        if (tid < NJ) {
            float s = 0.f;
            for (int k = 0; k < NJ; ++k) s += A[tid * NJ + k];
            d[tid] = s;
            dw[tid] = s - A[tid * NJ + tid];  // Aw = A - I row sum
        }
        __syncthreads();
        for (int idx = tid; idx < NJ * NJ; idx += blockDim.x) {
            int j = idx / NJ, k = idx % NJ;
            g_An[idx] = A[idx] * rsqrtf(d[j] * d[k]);
            g_A2[idx] = (j == k) ? dw[j] : -A[idx];
        }
    }
    int gtid = blockIdx.x * blockDim.x + tid;
    int stride = gridDim.x * blockDim.x;
    // Wsym[(c1*17+d)*32 + o]: symmetric pair coefficients of W3[o, c1*32+c2]
    for (int idx = gtid; idx < 544 * 32; idx += stride) {
        int r = idx >> 5, o = idx & 31;
        int c1 = r / 17, dd = r % 17;
        int c2 = (c1 + dd) & 31;
        float v;
        if (dd == 0) {
            v = W3[o * 1024 + c1 * 32 + c1];
        } else {
            v = W3[o * 1024 + c1 * 32 + c2] + W3[o * 1024 + c2 * 32 + c1];
            if (dd == 16) v *= 0.5f;  // pairs with distance 16 enumerated twice
        }
        g_Wsym[r * 32 + o] = v;
    }
    // Wt hi/lo tf32 split (layout [o][i*3+dt] == natural Wt layout)
    for (int idx = gtid; idx < 64 * 288; idx += stride) {
        float w = Wt[idx];
        uint32_t h = f2tf32(w);
        float hf = __uint_as_float(h);
        uint32_t l = f2tf32(w - hf);
        g_WAh[idx] = hf;
        g_WAl[idx] = __uint_as_float(l);
    }
}

// ---------------------------------------------------------------------------
// K1: per (b, 4-t chunk): graph convs + pw convs + quadratic-form branch
// grid = 16 * 32 = 512 blocks, 256 threads  (unchanged from round 2)
// ---------------------------------------------------------------------------
__global__ void __launch_bounds__(256) k1_branches(
    const float* __restrict__ x,
    const float* __restrict__ W1, const float* __restrict__ b1,
    const float* __restrict__ W2, const float* __restrict__ b2,
    const float* __restrict__ b3) {
    __shared__ float sA[32 * 100];   // x slice, later G1
    __shared__ float sB[32 * 100];   // G2
    __shared__ float sAn[NJ * NJ];
    __shared__ float sA2[NJ * NJ];
    __shared__ float sW1[32 * 32];
    __shared__ float sW2[32 * 32];

    int tid = threadIdx.x;
    int b = blockIdx.x >> 5;
    int t0 = (blockIdx.x & 31) * 4;

    for (int idx = tid; idx < 3200; idx += 256) {
        int c = idx / 100, q = idx % 100;
        int tt = q / 25, j = q % 25;
        sA[idx] = x[((b * 32 + c) * 128 + t0 + tt) * 25 + j];
    }
    for (int idx = tid; idx < NJ * NJ; idx += 256) {
        sAn[idx] = g_An[idx];
        sA2[idx] = g_A2[idx];
    }
    for (int idx = tid; idx < 1024; idx += 256) {
        sW1[idx] = W1[idx];
        sW2[idx] = W2[idx];
    }
    __syncthreads();

    float r1[13], r2[13];
#pragma unroll
    for (int it = 0; it < 13; ++it) {
        int idx = tid + it * 256;
        float a1 = 0.f, a2 = 0.f;
        if (idx < 3200) {
            int c = idx / 100, q = idx % 100;
            int tt = q / 25, k = q % 25;
            const float* xr = &sA[c * 100 + tt * 25];
#pragma unroll
            for (int j = 0; j < 25; ++j) {
                float xv = xr[j];
                a1 += xv * sAn[j * 25 + k];
                a2 += xv * sA2[j * 25 + k];
            }
        }
        r1[it] = a1;
        r2[it] = a2;
    }
    __syncthreads();
#pragma unroll
    for (int it = 0; it < 13; ++it) {
        int idx = tid + it * 256;
        if (idx < 3200) { sA[idx] = r1[it]; sB[idx] = r2[it]; }
    }
    __syncthreads();

    for (int idx = tid; idx < 6400; idx += 256) {
        int which = idx >= 3200 ? 1 : 0;
        int r = idx - which * 3200;
        int o = r / 100, p = r % 100;
        const float* G = which ? sB : sA;
        const float* W = which ? &sW2[o * 32] : &sW1[o * 32];
        float acc = which ? __ldg(&b2[o]) : __ldg(&b1[o]);
#pragma unroll
        for (int c = 0; c < 32; ++c) acc += W[c] * G[c * 100 + p];
        acc = fmaxf(acc, 0.f);
        int tt = p / 25, k = p % 25;
        g_xc[((b * 96 + which * 32 + o) * 128 + t0 + tt) * 25 + k] = acc;
    }

    // quadratic form via symmetric pairs, o-tile=8, pos-tile=2
    int og = tid >> 6;
    int pg = tid & 63;
    int ob = og * 8;
    int p0 = pg;
    bool has1 = (pg < 36);
    int p1 = has1 ? pg + 64 : pg;

    float acc0[8] = {0, 0, 0, 0, 0, 0, 0, 0};
    float acc1[8] = {0, 0, 0, 0, 0, 0, 0, 0};
    const float4* Ws4 = reinterpret_cast<const float4*>(g_Wsym);
    int oq = og * 2;

#pragma unroll 1
    for (int c1 = 0; c1 < 32; ++c1) {
        float u0 = sB[c1 * 100 + p0];
        float u1 = sB[c1 * 100 + p1];
        int rbase = (c1 * 17) * 8 + oq;
#pragma unroll
        for (int dd = 0; dd < 17; ++dd) {
            int c2 = (c1 + dd) & 31;
            const float* row = &sB[c2 * 100];
            float q0 = u0 * row[p0];
            float q1 = u1 * row[p1];
            float4 wa = __ldg(&Ws4[rbase + dd * 8]);
            float4 wb = __ldg(&Ws4[rbase + dd * 8 + 1]);
            acc0[0] += wa.x * q0; acc0[1] += wa.y * q0;
            acc0[2] += wa.z * q0; acc0[3] += wa.w * q0;
            acc0[4] += wb.x * q0; acc0[5] += wb.y * q0;
            acc0[6] += wb.z * q0; acc0[7] += wb.w * q0;
            acc1[0] += wa.x * q1; acc1[1] += wa.y * q1;
            acc1[2] += wa.z * q1; acc1[3] += wa.w * q1;
            acc1[4] += wb.x * q1; acc1[5] += wb.y * q1;
            acc1[6] += wb.z * q1; acc1[7] += wb.w * q1;
        }
    }

    float bb[8];
#pragma unroll
    for (int o = 0; o < 8; ++o) bb[o] = __ldg(&b3[ob + o]);

    {
        int tt = p0 / 25, k = p0 % 25;
#pragma unroll
        for (int o = 0; o < 8; ++o) {
            float v = fmaxf(acc0[o] + bb[o], 0.f);
            g_xc[((b * 96 + 64 + ob + o) * 128 + t0 + tt) * 25 + k] = v;
        }
    }
    if (has1) {
        int tt = p1 / 25, k = p1 % 25;
#pragma unroll
        for (int o = 0; o < 8; ++o) {
            float v = fmaxf(acc1[o] + bb[o], 0.f);
            g_xc[((b * 96 + 64 + ob + o) * 128 + t0 + tt) * 25 + k] = v;
        }
    }
}

// ---------------------------------------------------------------------------
// K2: temporal conv as GEMM on tensor cores (3xTF32 mma.sync).
// GEMM per block: Y[64, 200] = Wt[64, 288] * im2col(xc)[288, 200]
// block = (b, 8 t's); 200 pos = 25 n8-tiles; 64 o = 4 m16-tiles; K=288.
// 8 warps: warp = m-tile (warp&3) x n-half (warp>>2, 13/12 n-tiles).
// Epilogue: bias + relu + store g_y + deterministic BN partials.
// ---------------------------------------------------------------------------
__global__ void __launch_bounds__(256) k2_tconv_mma(const float* __restrict__ bt) {
    extern __shared__ float sxc[];  // [96][250]: 10 t's (t0-1..t0+8) x 25 j
    int tid = threadIdx.x;
    int b = blockIdx.x >> 4;
    int t0 = (blockIdx.x & 15) * 8;

    // load xc tile: per channel 250 contiguous floats starting at (t0-1)*25
    for (int idx = tid; idx < 24000; idx += 256) {
        int i = idx / 250, q = idx % 250;
        int gq = (t0 - 1) * 25 + q;
        sxc[idx] = (gq >= 0 && gq < 3200) ? g_xc[(b * 96 + i) * 3200 + gq] : 0.f;
    }
    __syncthreads();

    int warp = tid >> 5, lane = tid & 31;
    int g = lane >> 2, c = lane & 3;
    int mt = warp & 3;
    int half = warp >> 2;
    int nt0 = half ? 13 : 0;
    int ntN = half ? 12 : 13;
    int o0 = mt * 16;
    int o_lo = o0 + g, o_hi = o0 + g + 8;

    float Cacc[13][4];
#pragma unroll
    for (int n = 0; n < 13; ++n) {
        Cacc[n][0] = 0.f; Cacc[n][1] = 0.f;
        Cacc[n][2] = 0.f; Cacc[n][3] = 0.f;
    }

    int posbase = nt0 * 8 + g;  // B col for this lane in n-tile n: posbase + n*8

#pragma unroll 1
    for (int kt = 0; kt < 36; ++kt) {
        int k0i = kt * 8 + c;
        int k1i = k0i + 4;
        int i0 = k0i / 3, dt0 = k0i - i0 * 3;
        int i1 = k1i / 3, dt1 = k1i - i1 * 3;
        int ba0 = i0 * 250 + dt0 * 25;
        int ba1 = i1 * 250 + dt1 * 25;

        uint32_t Ah0 = __float_as_uint(g_WAh[o_lo * 288 + k0i]);
        uint32_t Ah1 = __float_as_uint(g_WAh[o_hi * 288 + k0i]);
        uint32_t Ah2 = __float_as_uint(g_WAh[o_lo * 288 + k1i]);
        uint32_t Ah3 = __float_as_uint(g_WAh[o_hi * 288 + k1i]);
        uint32_t Al0 = __float_as_uint(g_WAl[o_lo * 288 + k0i]);
        uint32_t Al1 = __float_as_uint(g_WAl[o_hi * 288 + k0i]);
        uint32_t Al2 = __float_as_uint(g_WAl[o_lo * 288 + k1i]);
        uint32_t Al3 = __float_as_uint(g_WAl[o_hi * 288 + k1i]);

#pragma unroll
        for (int n = 0; n < 13; ++n) {
            if (n < ntN) {
                int posb = posbase + n * 8;
                float x0 = sxc[ba0 + posb];
                float x1 = sxc[ba1 + posb];
                uint32_t bh0 = f2tf32(x0);
                uint32_t bh1 = f2tf32(x1);
                uint32_t bl0 = f2tf32(x0 - __uint_as_float(bh0));
                uint32_t bl1 = f2tf32(x1 - __uint_as_float(bh1));
                mma_tf32(Cacc[n], Ah0, Ah1, Ah2, Ah3, bh0, bh1);
                mma_tf32(Cacc[n], Al0, Al1, Al2, Al3, bh0, bh1);
                mma_tf32(Cacc[n], Ah0, Ah1, Ah2, Ah3, bl0, bl1);
            }
        }
    }

    // epilogue: bias + relu + store + BN partial accumulation
    float blo = __ldg(&bt[o_lo]), bhi = __ldg(&bt[o_hi]);
    float sl = 0.f, sl2 = 0.f, sh = 0.f, sh2 = 0.f;
    float* ylo = &g_y[(b * 64 + o_lo) * 3200 + t0 * 25];
    float* yhi = &g_y[(b * 64 + o_hi) * 3200 + t0 * 25];
#pragma unroll
    for (int n = 0; n < 13; ++n) {
        if (n < ntN) {
            int col = (nt0 + n) * 8 + 2 * c;
            float y0 = fmaxf(Cacc[n][0] + blo, 0.f);
            float y1 = fmaxf(Cacc[n][1] + blo, 0.f);
            float y2 = fmaxf(Cacc[n][2] + bhi, 0.f);
            float y3 = fmaxf(Cacc[n][3] + bhi, 0.f);
            *reinterpret_cast<float2*>(ylo + col) = make_float2(y0, y1);
            *reinterpret_cast<float2*>(yhi + col) = make_float2(y2, y3);
            sl += y0 + y1; sl2 += y0 * y0 + y1 * y1;
            sh += y2 + y3; sh2 += y2 * y2 + y3 * y3;
        }
    }
#pragma unroll
    for (int off = 1; off < 4; off <<= 1) {
        sl  += __shfl_xor_sync(0xffffffffu, sl,  off);
        sl2 += __shfl_xor_sync(0xffffffffu, sl2, off);
        sh  += __shfl_xor_sync(0xffffffffu, sh,  off);
        sh2 += __shfl_xor_sync(0xffffffffu, sh2, off);
    }
    __syncthreads();  // done reading sxc tile; reuse as reduction buffer
    if (c == 0) {
        sxc[half * 64 + o_lo] = sl;
        sxc[half * 64 + o_hi] = sh;
        sxc[128 + half * 64 + o_lo] = sl2;
        sxc[128 + half * 64 + o_hi] = sh2;
    }
    __syncthreads();
    if (tid < 64) {
        g_part[tid * 256 + blockIdx.x] = sxc[tid] + sxc[64 + tid];
        g_part[(64 + tid) * 256 + blockIdx.x] = sxc[128 + tid] + sxc[192 + tid];
    }
}

// ---------------------------------------------------------------------------
// K3: BN stats -> scale/shift. grid = 64 (one per channel), 32 threads
// ---------------------------------------------------------------------------
__global__ void k3_stats(const float* __restrict__ gamma,
                         const float* __restrict__ beta) {
    int o = blockIdx.x, lane = threadIdx.x;
    const float4* ps = reinterpret_cast<const float4*>(&g_part[o * 256]);
    const float4* pq = reinterpret_cast<const float4*>(&g_part[(64 + o) * 256]);
    float4 a0 = ps[lane], a1 = ps[lane + 32];
    float4 b0 = pq[lane], b1 = pq[lane + 32];
    float s = (a0.x + a0.y) + (a0.z + a0.w) + (a1.x + a1.y) + (a1.z + a1.w);
    float q = (b0.x + b0.y) + (b0.z + b0.w) + (b1.x + b1.y) + (b1.z + b1.w);
#pragma unroll
    for (int off = 16; off > 0; off >>= 1) {
        s += __shfl_xor_sync(0xffffffffu, s, off);
        q += __shfl_xor_sync(0xffffffffu, q, off);
    }
    if (lane == 0) {
        const float N = (float)(NB * NT * NJ);
        float mean = s / N;
        float var = q / N - mean * mean;
        float sc = __ldg(&gamma[o]) * rsqrtf(var + EPSBN);
        g_scsh[o] = sc;
        g_scsh[64 + o] = __ldg(&beta[o]) - mean * sc;
    }
}

// ---------------------------------------------------------------------------
// K4: affine normalize to output (float4)
// ---------------------------------------------------------------------------
__global__ void k4_norm(float* __restrict__ out) {
    int idx = blockIdx.x * blockDim.x + threadIdx.x;  // float4 index
    const int total4 = NB * NO * NT * NJ / 4;         // 819200
    if (idx >= total4) return;
    int ch = (idx / 800) & 63;
    float sc = g_scsh[ch], sh = g_scsh[64 + ch];
    const float4* y4 = reinterpret_cast<const float4*>(g_y);
    float4 v = y4[idx];
    v.x = sc * v.x + sh;
    v.y = sc * v.y + sh;
    v.z = sc * v.z + sh;
    v.w = sc * v.w + sh;
    reinterpret_cast<float4*>(out)[idx] = v;
}

// ---------------------------------------------------------------------------
extern "C" void kernel_launch(void* const* d_in, const int* in_sizes, int n_in,
                              void* d_out, int out_size) {
    const float* x = (const float*)d_in[0];
    const float* A = (const float*)d_in[1];
    const float* W1 = (const float*)d_in[2];
    const float* b1 = (const float*)d_in[3];
    const float* W2 = (const float*)d_in[4];
    const float* b2 = (const float*)d_in[5];
    const float* W3 = (const float*)d_in[6];
    const float* b3 = (const float*)d_in[7];
    const float* Wt = (const float*)d_in[8];
    const float* bt = (const float*)d_in[9];
    const float* gamma = (const float*)d_in[10];
    const float* beta = (const float*)d_in[11];

    const int k2_smem = 24000 * sizeof(float);  // 96 KB dynamic
    cudaFuncSetAttribute(k2_tconv_mma,
                         cudaFuncAttributeMaxDynamicSharedMemorySize, k2_smem);

    k0_prep<<<64, 256>>>(A, W3, Wt);
    k1_branches<<<512, 256>>>(x, W1, b1, W2, b2, b3);
    k2_tconv_mma<<<256, 256, k2_smem>>>(bt);
    k3_stats<<<64, 32>>>(gamma, beta);
    k4_norm<<<3200, 256>>>((float*)d_out);
}

// round 4
// speedup vs baseline: 1.8043x; 1.1961x over previous
#include <cuda_runtime.h>
#include <cstdint>

// ---------------------------------------------------------------------------
// GCN_OUTPRODUCT: B=16, C=32, T=128, J=25, O=64
// ---------------------------------------------------------------------------

#define NB 16
#define NC 32
#define NT 128
#define NJ 25
#define NO 64
#define EPSBN 1e-5f

// scratch (static device allocations; allowed)
__device__ __align__(16) float g_An[NJ * NJ];
__device__ __align__(16) float g_A2[NJ * NJ];
__device__ __align__(16) float g_WQ[32 * 544 * 2];      // [o][r]{hi,lo} qform W
__device__ __align__(16) float g_WAh[64 * 288];         // Wt tf32 hi, [o][k]
__device__ __align__(16) float g_WAl[64 * 288];         // Wt tf32 lo, [o][k]
__device__ __align__(16) float g_xc[NB * 96 * NT * NJ]; // concat branches
__device__ __align__(16) float g_y[NB * NO * NT * NJ];  // post-relu conv out
__device__ __align__(16) float g_part[128 * 256];       // [chan-stat][block]
__device__ __align__(16) float g_scsh[128];             // scale / shift

// ---------------------------------------------------------------------------
// mma.sync tf32 helpers
// ---------------------------------------------------------------------------
__device__ __forceinline__ uint32_t f2tf32(float x) {
    uint32_t r;
    asm("cvt.rna.tf32.f32 %0, %1;" : "=r"(r) : "f"(x));
    return r;
}

__device__ __forceinline__ void mma_tf32(float* d,
                                         uint32_t a0, uint32_t a1,
                                         uint32_t a2, uint32_t a3,
                                         uint32_t b0, uint32_t b1) {
    asm volatile(
        "mma.sync.aligned.m16n8k8.row.col.f32.tf32.tf32.f32 "
        "{%0,%1,%2,%3}, {%4,%5,%6,%7}, {%8,%9}, {%0,%1,%2,%3};"
        : "+f"(d[0]), "+f"(d[1]), "+f"(d[2]), "+f"(d[3])
        : "r"(a0), "r"(a1), "r"(a2), "r"(a3), "r"(b0), "r"(b1));
}

// ---------------------------------------------------------------------------
// K0: graph matrices + symmetrized-split W3 + tf32 hi/lo split of Wt
// ---------------------------------------------------------------------------
__global__ void k0_prep(const float* __restrict__ A,
                        const float* __restrict__ W3,
                        const float* __restrict__ Wt) {
    int tid = threadIdx.x;
    if (blockIdx.x == 0) {
        __shared__ float d[NJ], dw[NJ];
        if (tid < NJ) {
            float s = 0.f;
            for (int k = 0; k < NJ; ++k) s += A[tid * NJ + k];
            d[tid] = s;
            dw[tid] = s - A[tid * NJ + tid];  // Aw = A - I row sum
        }
        __syncthreads();
        for (int idx = tid; idx < NJ * NJ; idx += blockDim.x) {
            int j = idx / NJ, k = idx % NJ;
            g_An[idx] = A[idx] * rsqrtf(d[j] * d[k]);
            g_A2[idx] = (j == k) ? dw[j] : -A[idx];
        }
    }
    int gtid = blockIdx.x * blockDim.x + tid;
    int stride = gridDim.x * blockDim.x;
    // g_WQ[o][r] = {hi,lo} of symmetric pair coeff; r=(c1*17+dd), c2=(c1+dd)&31
    for (int idx = gtid; idx < 32 * 544; idx += stride) {
        int o = idx / 544, r = idx % 544;
        int c1 = r / 17, dd = r % 17;
        int c2 = (c1 + dd) & 31;
        float v;
        if (dd == 0) {
            v = W3[o * 1024 + c1 * 32 + c1];
        } else {
            v = W3[o * 1024 + c1 * 32 + c2] + W3[o * 1024 + c2 * 32 + c1];
            if (dd == 16) v *= 0.5f;  // distance-16 pairs enumerated twice
        }
        uint32_t h = f2tf32(v);
        float hf = __uint_as_float(h);
        g_WQ[idx * 2] = hf;
        g_WQ[idx * 2 + 1] = __uint_as_float(f2tf32(v - hf));
    }
    // Wt hi/lo tf32 split (layout [o][i*3+dt] == natural Wt layout)
    for (int idx = gtid; idx < 64 * 288; idx += stride) {
        float w = Wt[idx];
        uint32_t h = f2tf32(w);
        float hf = __uint_as_float(h);
        g_WAh[idx] = hf;
        g_WAl[idx] = __uint_as_float(f2tf32(w - hf));
    }
}

// ---------------------------------------------------------------------------
// K1: per (b, 4-t chunk): graph convs + pw convs + qform via tensor cores
// grid = 16 * 32 = 512 blocks, 256 threads
// smem tiles use STRIDE=104 (100 positions + 4 zero pad -> 13 n8-tiles)
// ---------------------------------------------------------------------------
#define STR 104
__global__ void __launch_bounds__(256) k1_branches(
    const float* __restrict__ x,
    const float* __restrict__ W1, const float* __restrict__ b1,
    const float* __restrict__ W2, const float* __restrict__ b2,
    const float* __restrict__ b3) {
    __shared__ float sA[32 * STR];   // x slice, later G1
    __shared__ float sB[32 * STR];   // G2
    __shared__ float sAn[NJ * NJ];
    __shared__ float sA2[NJ * NJ];
    __shared__ float sW1[32 * 32];
    __shared__ float sW2[32 * 32];
    __shared__ uint32_t soff[544];   // packed (c1*STR)<<16 | (c2*STR)

    int tid = threadIdx.x;
    int b = blockIdx.x >> 5;
    int t0 = (blockIdx.x & 31) * 4;

    // load x slice [c][col], zero pad cols 100..103 (both tiles)
    for (int idx = tid; idx < 32 * STR; idx += 256) {
        int c = idx / STR, q = idx % STR;
        float v = 0.f;
        if (q < 100) {
            int tt = q / 25, j = q % 25;
            v = x[((b * 32 + c) * 128 + t0 + tt) * 25 + j];
        }
        sA[idx] = v;
        if (q >= 100) sB[idx] = 0.f;
    }
    for (int idx = tid; idx < NJ * NJ; idx += 256) {
        sAn[idx] = g_An[idx];
        sA2[idx] = g_A2[idx];
    }
    for (int idx = tid; idx < 1024; idx += 256) {
        sW1[idx] = W1[idx];
        sW2[idx] = W2[idx];
    }
    for (int idx = tid; idx < 544; idx += 256) {
        int c1 = idx / 17, dd = idx % 17;
        int c2 = (c1 + dd) & 31;
        soff[idx] = ((uint32_t)(c1 * STR) << 16) | (uint32_t)(c2 * STR);
    }
    __syncthreads();

    // graph convs -> registers (so G1 can overwrite x buffer)
    float r1[13], r2[13];
#pragma unroll
    for (int it = 0; it < 13; ++it) {
        int idx = tid + it * 256;
        float a1 = 0.f, a2 = 0.f;
        if (idx < 3200) {
            int c = idx / 100, q = idx % 100;
            int tt = q / 25, k = q % 25;
            const float* xr = &sA[c * STR + tt * 25];
#pragma unroll
            for (int j = 0; j < 25; ++j) {
                float xv = xr[j];
                a1 += xv * sAn[j * 25 + k];
                a2 += xv * sA2[j * 25 + k];
            }
        }
        r1[it] = a1;
        r2[it] = a2;
    }
    __syncthreads();
#pragma unroll
    for (int it = 0; it < 13; ++it) {
        int idx = tid + it * 256;
        if (idx < 3200) {
            int c = idx / 100, q = idx % 100;
            sA[c * STR + q] = r1[it];
            sB[c * STR + q] = r2[it];
        }
    }
    __syncthreads();

    // pointwise convs: x1o (channels 0..31), x2o (channels 32..63)
    for (int idx = tid; idx < 6400; idx += 256) {
        int which = idx >= 3200 ? 1 : 0;
        int r = idx - which * 3200;
        int o = r / 100, p = r % 100;
        const float* G = which ? sB : sA;
        const float* W = which ? &sW2[o * 32] : &sW1[o * 32];
        float acc = which ? __ldg(&b2[o]) : __ldg(&b1[o]);
#pragma unroll
        for (int c = 0; c < 32; ++c) acc += W[c] * G[c * STR + p];
        acc = fmaxf(acc, 0.f);
        int tt = p / 25, k = p % 25;
        g_xc[((b * 96 + which * 32 + o) * 128 + t0 + tt) * 25 + k] = acc;
    }

    // ---- quadratic form on tensor cores ----
    // C[32,100] = WQ^T[32,544] x Q[544,100], Q[r,p] = v_c1[p]*v_c2[p]
    // 8 warps: m-tile = warp&1 (16 o's), n-group = warp>>1 -> n-tiles
    // {0..3},{4..6},{7..9},{10..12}; 68 k-tiles.
    int warp = tid >> 5, lane = tid & 31;
    int g = lane >> 2, c = lane & 3;
    int mt = warp & 1;
    int nq = warp >> 1;
    int nt0 = (nq == 0) ? 0 : (1 + 3 * nq);
    int ntN = (nq == 0) ? 4 : 3;
    int o0 = mt * 16;
    int olo = o0 + g, ohi = o0 + g + 8;

    float Cq[4][4];
#pragma unroll
    for (int n = 0; n < 4; ++n) {
        Cq[n][0] = 0.f; Cq[n][1] = 0.f; Cq[n][2] = 0.f; Cq[n][3] = 0.f;
    }

    const float2* WQ2 = reinterpret_cast<const float2*>(g_WQ);

#pragma unroll 2
    for (int kt = 0; kt < 68; ++kt) {
        int r0 = kt * 8 + c, r1i = r0 + 4;
        uint32_t pk0 = soff[r0], pk1 = soff[r1i];
        int a0o = pk0 >> 16, a0t = pk0 & 0xffff;
        int a1o = pk1 >> 16, a1t = pk1 & 0xffff;
        float2 w0 = __ldg(&WQ2[olo * 544 + r0]);
        float2 w1 = __ldg(&WQ2[ohi * 544 + r0]);
        float2 w2 = __ldg(&WQ2[olo * 544 + r1i]);
        float2 w3 = __ldg(&WQ2[ohi * 544 + r1i]);
        uint32_t Ah0 = __float_as_uint(w0.x), Al0 = __float_as_uint(w0.y);
        uint32_t Ah1 = __float_as_uint(w1.x), Al1 = __float_as_uint(w1.y);
        uint32_t Ah2 = __float_as_uint(w2.x), Al2 = __float_as_uint(w2.y);
        uint32_t Ah3 = __float_as_uint(w3.x), Al3 = __float_as_uint(w3.y);

#pragma unroll
        for (int n = 0; n < 4; ++n) {
            if (n < ntN) {
                int p = (nt0 + n) * 8 + g;
                float q0 = sB[a0o + p] * sB[a0t + p];
                float q1 = sB[a1o + p] * sB[a1t + p];
                uint32_t bh0 = f2tf32(q0);
                uint32_t bh1 = f2tf32(q1);
                uint32_t bl0 = f2tf32(q0 - __uint_as_float(bh0));
                uint32_t bl1 = f2tf32(q1 - __uint_as_float(bh1));
                mma_tf32(Cq[n], Ah0, Ah1, Ah2, Ah3, bh0, bh1);
                mma_tf32(Cq[n], Al0, Al1, Al2, Al3, bh0, bh1);
                mma_tf32(Cq[n], Ah0, Ah1, Ah2, Ah3, bl0, bl1);
            }
        }
    }

    // epilogue: bias + relu + store to g_xc channels 64..95
    float blo = __ldg(&b3[olo]), bhi = __ldg(&b3[ohi]);
#pragma unroll
    for (int n = 0; n < 4; ++n) {
        if (n < ntN) {
            int col = (nt0 + n) * 8 + 2 * c;
            if (col < 100) {
                int tt = col / 25, k = col % 25;
                g_xc[((b * 96 + 64 + olo) * 128 + t0 + tt) * 25 + k] =
                    fmaxf(Cq[n][0] + blo, 0.f);
                g_xc[((b * 96 + 64 + ohi) * 128 + t0 + tt) * 25 + k] =
                    fmaxf(Cq[n][2] + bhi, 0.f);
            }
            int col1 = col + 1;
            if (col1 < 100) {
                int tt = col1 / 25, k = col1 % 25;
                g_xc[((b * 96 + 64 + olo) * 128 + t0 + tt) * 25 + k] =
                    fmaxf(Cq[n][1] + blo, 0.f);
                g_xc[((b * 96 + 64 + ohi) * 128 + t0 + tt) * 25 + k] =
                    fmaxf(Cq[n][3] + bhi, 0.f);
            }
        }
    }
}

// ---------------------------------------------------------------------------
// K2: temporal conv as GEMM on tensor cores (3xTF32 mma.sync). Unchanged.
// ---------------------------------------------------------------------------
__global__ void __launch_bounds__(256) k2_tconv_mma(const float* __restrict__ bt) {
    extern __shared__ float sxc[];  // [96][250]: 10 t's (t0-1..t0+8) x 25 j
    int tid = threadIdx.x;
    int b = blockIdx.x >> 4;
    int t0 = (blockIdx.x & 15) * 8;

    for (int idx = tid; idx < 24000; idx += 256) {
        int i = idx / 250, q = idx % 250;
        int gq = (t0 - 1) * 25 + q;
        sxc[idx] = (gq >= 0 && gq < 3200) ? g_xc[(b * 96 + i) * 3200 + gq] : 0.f;
    }
    __syncthreads();

    int warp = tid >> 5, lane = tid & 31;
    int g = lane >> 2, c = lane & 3;
    int mt = warp & 3;
    int half = warp >> 2;
    int nt0 = half ? 13 : 0;
    int ntN = half ? 12 : 13;
    int o0 = mt * 16;
    int o_lo = o0 + g, o_hi = o0 + g + 8;

    float Cacc[13][4];
#pragma unroll
    for (int n = 0; n < 13; ++n) {
        Cacc[n][0] = 0.f; Cacc[n][1] = 0.f;
        Cacc[n][2] = 0.f; Cacc[n][3] = 0.f;
    }

    int posbase = nt0 * 8 + g;

#pragma unroll 1
    for (int kt = 0; kt < 36; ++kt) {
        int k0i = kt * 8 + c;
        int k1i = k0i + 4;
        int i0 = k0i / 3, dt0 = k0i - i0 * 3;
        int i1 = k1i / 3, dt1 = k1i - i1 * 3;
        int ba0 = i0 * 250 + dt0 * 25;
        int ba1 = i1 * 250 + dt1 * 25;

        uint32_t Ah0 = __float_as_uint(g_WAh[o_lo * 288 + k0i]);
        uint32_t Ah1 = __float_as_uint(g_WAh[o_hi * 288 + k0i]);
        uint32_t Ah2 = __float_as_uint(g_WAh[o_lo * 288 + k1i]);
        uint32_t Ah3 = __float_as_uint(g_WAh[o_hi * 288 + k1i]);
        uint32_t Al0 = __float_as_uint(g_WAl[o_lo * 288 + k0i]);
        uint32_t Al1 = __float_as_uint(g_WAl[o_hi * 288 + k0i]);
        uint32_t Al2 = __float_as_uint(g_WAl[o_lo * 288 + k1i]);
        uint32_t Al3 = __float_as_uint(g_WAl[o_hi * 288 + k1i]);

#pragma unroll
        for (int n = 0; n < 13; ++n) {
            if (n < ntN) {
                int posb = posbase + n * 8;
                float x0 = sxc[ba0 + posb];
                float x1 = sxc[ba1 + posb];
                uint32_t bh0 = f2tf32(x0);
                uint32_t bh1 = f2tf32(x1);
                uint32_t bl0 = f2tf32(x0 - __uint_as_float(bh0));
                uint32_t bl1 = f2tf32(x1 - __uint_as_float(bh1));
                mma_tf32(Cacc[n], Ah0, Ah1, Ah2, Ah3, bh0, bh1);
                mma_tf32(Cacc[n], Al0, Al1, Al2, Al3, bh0, bh1);
                mma_tf32(Cacc[n], Ah0, Ah1, Ah2, Ah3, bl0, bl1);
            }
        }
    }

    float blo = __ldg(&bt[o_lo]), bhi = __ldg(&bt[o_hi]);
    float sl = 0.f, sl2 = 0.f, sh = 0.f, sh2 = 0.f;
    float* ylo = &g_y[(b * 64 + o_lo) * 3200 + t0 * 25];
    float* yhi = &g_y[(b * 64 + o_hi) * 3200 + t0 * 25];
#pragma unroll
    for (int n = 0; n < 13; ++n) {
        if (n < ntN) {
            int col = (nt0 + n) * 8 + 2 * c;
            float y0 = fmaxf(Cacc[n][0] + blo, 0.f);
            float y1 = fmaxf(Cacc[n][1] + blo, 0.f);
            float y2 = fmaxf(Cacc[n][2] + bhi, 0.f);
            float y3 = fmaxf(Cacc[n][3] + bhi, 0.f);
            *reinterpret_cast<float2*>(ylo + col) = make_float2(y0, y1);
            *reinterpret_cast<float2*>(yhi + col) = make_float2(y2, y3);
            sl += y0 + y1; sl2 += y0 * y0 + y1 * y1;
            sh += y2 + y3; sh2 += y2 * y2 + y3 * y3;
        }
    }
#pragma unroll
    for (int off = 1; off < 4; off <<= 1) {
        sl  += __shfl_xor_sync(0xffffffffu, sl,  off);
        sl2 += __shfl_xor_sync(0xffffffffu, sl2, off);
        sh  += __shfl_xor_sync(0xffffffffu, sh,  off);
        sh2 += __shfl_xor_sync(0xffffffffu, sh2, off);
    }
    __syncthreads();
    if (c == 0) {
        sxc[half * 64 + o_lo] = sl;
        sxc[half * 64 + o_hi] = sh;
        sxc[128 + half * 64 + o_lo] = sl2;
        sxc[128 + half * 64 + o_hi] = sh2;
    }
    __syncthreads();
    if (tid < 64) {
        g_part[tid * 256 + blockIdx.x] = sxc[tid] + sxc[64 + tid];
        g_part[(64 + tid) * 256 + blockIdx.x] = sxc[128 + tid] + sxc[192 + tid];
    }
}

// ---------------------------------------------------------------------------
// K3: BN stats -> scale/shift. grid = 64 (one per channel), 32 threads
// ---------------------------------------------------------------------------
__global__ void k3_stats(const float* __restrict__ gamma,
                         const float* __restrict__ beta) {
    int o = blockIdx.x, lane = threadIdx.x;
    const float4* ps = reinterpret_cast<const float4*>(&g_part[o * 256]);
    const float4* pq = reinterpret_cast<const float4*>(&g_part[(64 + o) * 256]);
    float4 a0 = ps[lane], a1 = ps[lane + 32];
    float4 b0 = pq[lane], b1 = pq[lane + 32];
    float s = (a0.x + a0.y) + (a0.z + a0.w) + (a1.x + a1.y) + (a1.z + a1.w);
    float q = (b0.x + b0.y) + (b0.z + b0.w) + (b1.x + b1.y) + (b1.z + b1.w);
#pragma unroll
    for (int off = 16; off > 0; off >>= 1) {
        s += __shfl_xor_sync(0xffffffffu, s, off);
        q += __shfl_xor_sync(0xffffffffu, q, off);
    }
    if (lane == 0) {
        const float N = (float)(NB * NT * NJ);
        float mean = s / N;
        float var = q / N - mean * mean;
        float sc = __ldg(&gamma[o]) * rsqrtf(var + EPSBN);
        g_scsh[o] = sc;
        g_scsh[64 + o] = __ldg(&beta[o]) - mean * sc;
    }
}

// ---------------------------------------------------------------------------
// K4: affine normalize to output (float4)
// ---------------------------------------------------------------------------
__global__ void k4_norm(float* __restrict__ out) {
    int idx = blockIdx.x * blockDim.x + threadIdx.x;
    const int total4 = NB * NO * NT * NJ / 4;
    if (idx >= total4) return;
    int ch = (idx / 800) & 63;
    float sc = g_scsh[ch], sh = g_scsh[64 + ch];
    const float4* y4 = reinterpret_cast<const float4*>(g_y);
    float4 v = y4[idx];
    v.x = sc * v.x + sh;
    v.y = sc * v.y + sh;
    v.z = sc * v.z + sh;
    v.w = sc * v.w + sh;
    reinterpret_cast<float4*>(out)[idx] = v;
}

// ---------------------------------------------------------------------------
extern "C" void kernel_launch(void* const* d_in, const int* in_sizes, int n_in,
                              void* d_out, int out_size) {
    const float* x = (const float*)d_in[0];
    const float* A = (const float*)d_in[1];
    const float* W1 = (const float*)d_in[2];
    const float* b1 = (const float*)d_in[3];
    const float* W2 = (const float*)d_in[4];
    const float* b2 = (const float*)d_in[5];
    const float* W3 = (const float*)d_in[6];
    const float* b3 = (const float*)d_in[7];
    const float* Wt = (const float*)d_in[8];
    const float* bt = (const float*)d_in[9];
    const float* gamma = (const float*)d_in[10];
    const float* beta = (const float*)d_in[11];

    const int k2_smem = 24000 * sizeof(float);  // 96 KB dynamic
    cudaFuncSetAttribute(k2_tconv_mma,
                         cudaFuncAttributeMaxDynamicSharedMemorySize, k2_smem);

    k0_prep<<<64, 256>>>(A, W3, Wt);
    k1_branches<<<512, 256>>>(x, W1, b1, W2, b2, b3);
    k2_tconv_mma<<<256, 256, k2_smem>>>(bt);
    k3_stats<<<64, 32>>>(gamma, beta);
    k4_norm<<<3200, 256>>>((float*)d_out);
}